// round 3
// baseline (speedup 1.0000x reference)
#include <cuda_runtime.h>
#include <math.h>

#define Bn 4
#define Cc 64
#define Hh 192
#define Ww 320
#define HW (Hh*Ww)

// ---------------- scratch (static __device__ arrays; no allocation) ----------------
__device__ float g_acc0[(size_t)Bn*65*HW];   // splat accum feat0 (+ones)
__device__ float g_acc1[(size_t)Bn*65*HW];   // splat accum feat1 (+ones)
__device__ float g_X   [(size_t)Bn*277*HW];  // concat input to conv1
__device__ float g_p1  [(size_t)Bn*160*HW];  // ping
__device__ float g_p2  [(size_t)Bn*128*HW];  // pong

// ---------------- zero accumulators ----------------
__global__ void zero_acc_kernel() {
    size_t i = (size_t)blockIdx.x * blockDim.x + threadIdx.x;
    if (i < (size_t)Bn*65*HW) { g_acc0[i] = 0.f; g_acc1[i] = 0.f; }
}

// ---------------- softsplat scatter (atomics) ----------------
__global__ void splat_kernel(const float* __restrict__ feat0,
                             const float* __restrict__ feat1,
                             const float* __restrict__ flow) {
    int idx = blockIdx.x * 256 + threadIdx.x;
    if (idx >= Bn*HW) return;
    int f = blockIdx.y;                 // 0: feat0/flow[:2], 1: feat1/flow[2:]
    int b = idx / HW, p = idx % HW;
    int y = p / Ww, x = p % Ww;
    const float* feat = f ? feat1 : feat0;
    float* acc = (f ? g_acc1 : g_acc0) + (size_t)b*65*HW;
    float u = flow[((size_t)b*4 + (f ? 2 : 0))*HW + p] * 0.125f;
    float v = flow[((size_t)b*4 + (f ? 3 : 1))*HW + p] * 0.125f;
    float tx = (float)x + u, ty = (float)y + v;
    float x0f = floorf(tx), y0f = floorf(ty);
    int ix0 = (int)x0f, iy0 = (int)y0f;
    float wx1 = tx - x0f,        wy1 = ty - y0f;
    float wx0 = (x0f + 1.f) - tx, wy0 = (y0f + 1.f) - ty;

    int offs[4]; float wts[4]; int n = 0;
    int   xs[2] = {ix0, ix0 + 1}, ys2[2] = {iy0, iy0 + 1};
    float wxa[2] = {wx0, wx1},    wya[2] = {wy0, wy1};
    #pragma unroll
    for (int cy = 0; cy < 2; cy++)
        #pragma unroll
        for (int cx = 0; cx < 2; cx++) {
            int xx = xs[cx], yy = ys2[cy];
            if (xx >= 0 && xx < Ww && yy >= 0 && yy < Hh) {
                offs[n] = yy*Ww + xx; wts[n] = wxa[cx]*wya[cy]; n++;
            }
        }
    const float* fb = feat + (size_t)b*64*HW + p;
    for (int c = 0; c < 65; c++) {
        float val = (c < 64) ? fb[(size_t)c*HW] : 1.f;
        float* ap = acc + (size_t)c*HW;
        for (int k = 0; k < n; k++) atomicAdd(ap + offs[k], val * wts[k]);
    }
}

// ---------------- normalize + assemble concat buffer X ----------------
// X channels: [0,81) corr (filled later), [81,145) f0, [145,209) f1,
//             [209,273) last_feat, [273,277) last_flow
__global__ void assemble_kernel(const float* __restrict__ last_feat,
                                const float* __restrict__ last_flow) {
    int idx = blockIdx.x * 256 + threadIdx.x;
    if (idx >= Bn*HW) return;
    int b = idx / HW, p = idx % HW;
    const float* a0 = g_acc0 + (size_t)b*65*HW + p;
    const float* a1 = g_acc1 + (size_t)b*65*HW + p;
    float n0 = a0[(size_t)64*HW]; n0 = (n0 == 0.f) ? 1.f : n0;
    float n1 = a1[(size_t)64*HW]; n1 = (n1 == 0.f) ? 1.f : n1;
    float* Xb = g_X + (size_t)b*277*HW + p;
    for (int c = 0; c < 64; c++) Xb[(size_t)(81 + c)*HW]  = a0[(size_t)c*HW] / n0;
    for (int c = 0; c < 64; c++) Xb[(size_t)(145 + c)*HW] = a1[(size_t)c*HW] / n1;
    const float* lf = last_feat + (size_t)b*64*HW + p;
    for (int c = 0; c < 64; c++) Xb[(size_t)(209 + c)*HW] = lf[(size_t)c*HW];
    const float* lw = last_flow + (size_t)b*4*HW + p;
    for (int c = 0; c < 4;  c++) Xb[(size_t)(273 + c)*HW] = lw[(size_t)c*HW];
}

// ---------------- correlation volume (81 displacements), lrelu ----------------
// grid: (W/16, H/16, B*9), block (16,16). z -> (b, dy index)
__global__ void corr_kernel() {
    int z = blockIdx.z;
    int b = z / 9, dyi = z % 9, dy = dyi - 4;
    int x0 = blockIdx.x * 16, y0 = blockIdx.y * 16;
    int tx = threadIdx.x, ty = threadIdx.y;
    __shared__ float s0[16][17];
    __shared__ float s1[16][25];
    float acc[9];
    #pragma unroll
    for (int d = 0; d < 9; d++) acc[d] = 0.f;
    const float* F0 = g_X + ((size_t)b*277 + 81)*HW;
    const float* F1 = g_X + ((size_t)b*277 + 145)*HW;
    int y = y0 + ty, x = x0 + tx;
    for (int c = 0; c < 64; c++) {
        s0[ty][tx] = F0[(size_t)c*HW + y*Ww + x];
        int ys = y + dy;
        int xs = x0 - 4 + tx;
        float v = 0.f;
        if (ys >= 0 && ys < Hh && xs >= 0 && xs < Ww) v = F1[(size_t)c*HW + ys*Ww + xs];
        s1[ty][tx] = v;
        if (tx < 8) {
            int xs2 = x0 + 12 + tx;
            float v2 = 0.f;
            if (ys >= 0 && ys < Hh && xs2 >= 0 && xs2 < Ww) v2 = F1[(size_t)c*HW + ys*Ww + xs2];
            s1[ty][16 + tx] = v2;
        }
        __syncthreads();
        float a = s0[ty][tx];
        #pragma unroll
        for (int d = 0; d < 9; d++) acc[d] += a * s1[ty][tx + d];
        __syncthreads();
    }
    float* V = g_X + (size_t)b*277*HW;
    #pragma unroll
    for (int d = 0; d < 9; d++) {
        float r = acc[d] * (1.f/64.f);
        r = (r > 0.f) ? r : 0.1f * r;
        V[(size_t)(dyi*9 + d)*HW + y*Ww + x] = r;
    }
}

// ---------------- conv1 (1x1, 277 -> 160, lrelu), X -> g_p1 ----------------
// grid (HW/256, B, 160/32), block 256, KO=32
__global__ void conv1x1_kernel(const float* __restrict__ wt,
                               const float* __restrict__ bias) {
    int p   = blockIdx.x * 256 + threadIdx.x;
    int b   = blockIdx.y;
    int ko0 = blockIdx.z * 32;
    __shared__ float wsm[16][32];
    float acc[32];
    #pragma unroll
    for (int k = 0; k < 32; k++) acc[k] = bias[ko0 + k];
    const float* Xb = g_X + (size_t)b*277*HW + p;
    for (int c0 = 0; c0 < 277; c0 += 16) {
        for (int i = threadIdx.x; i < 512; i += 256) {
            int ci = i >> 5, ko = i & 31;
            int cin = c0 + ci;
            wsm[ci][ko] = (cin < 277) ? wt[(size_t)(ko0 + ko)*277 + cin] : 0.f;
        }
        __syncthreads();
        int cmax = 277 - c0; if (cmax > 16) cmax = 16;
        for (int ci = 0; ci < cmax; ci++) {
            float v = Xb[(size_t)(c0 + ci)*HW];
            const float4* wrow = reinterpret_cast<const float4*>(wsm[ci]);
            #pragma unroll
            for (int k4 = 0; k4 < 8; k4++) {
                float4 w = wrow[k4];
                acc[4*k4+0] += v * w.x;
                acc[4*k4+1] += v * w.y;
                acc[4*k4+2] += v * w.z;
                acc[4*k4+3] += v * w.w;
            }
        }
        __syncthreads();
    }
    float* out = g_p1 + (size_t)b*160*HW + p;
    #pragma unroll
    for (int k = 0; k < 32; k++) {
        float r = acc[k];
        r = (r > 0.f) ? r : 0.1f * r;
        out[(size_t)(ko0 + k)*HW] = r;
    }
}

// ---------------- generic 3x3 conv (pad=1), 2 pixels/thread, KO outs ----------------
// grid (W/32, H/16, B*(COUT/KO)), block (16,16)
template<int CIN, int COUT, int KO, bool RELU>
__global__ void conv3x3_kernel(const float* __restrict__ src,
                               const float* __restrict__ wt,
                               const float* __restrict__ bias,
                               float* __restrict__ dst) {
    constexpr int NG = COUT / KO;
    int b   = blockIdx.z / NG;
    int ko0 = (blockIdx.z % NG) * KO;
    int x0  = blockIdx.x * 32, y0 = blockIdx.y * 16;
    int tx  = threadIdx.x, ty = threadIdx.y;
    int tid = ty * 16 + tx;
    __shared__ float s[18][35];
    __shared__ float wsm[KO][12];   // padded rows for aligned float4 reads
    float acc0[KO], acc1[KO];
    #pragma unroll
    for (int k = 0; k < KO; k++) { float bv = bias[ko0 + k]; acc0[k] = bv; acc1[k] = bv; }
    const float* S = src + (size_t)b*CIN*HW;
    for (int c = 0; c < CIN; c++) {
        const float* Sc = S + (size_t)c*HW;
        for (int i = tid; i < 612; i += 256) {   // 18 x 34 tile
            int r = i / 34, cc = i % 34;
            int gy = y0 - 1 + r, gx = x0 - 1 + cc;
            float v = 0.f;
            if (gy >= 0 && gy < Hh && gx >= 0 && gx < Ww) v = Sc[gy*Ww + gx];
            s[r][cc] = v;
        }
        if (tid < KO * 9)
            wsm[tid / 9][tid % 9] = wt[((size_t)(ko0 + tid/9)*CIN + c)*9 + tid % 9];
        __syncthreads();
        float in[3][4];
        #pragma unroll
        for (int r = 0; r < 3; r++)
            #pragma unroll
            for (int q = 0; q < 4; q++) in[r][q] = s[ty + r][2*tx + q];
        #pragma unroll
        for (int k = 0; k < KO; k++) {
            float4 wa = *reinterpret_cast<const float4*>(&wsm[k][0]);
            float4 wb = *reinterpret_cast<const float4*>(&wsm[k][4]);
            float  wc = wsm[k][8];
            acc0[k] += in[0][0]*wa.x + in[0][1]*wa.y + in[0][2]*wa.z
                     + in[1][0]*wa.w + in[1][1]*wb.x + in[1][2]*wb.y
                     + in[2][0]*wb.z + in[2][1]*wb.w + in[2][2]*wc;
            acc1[k] += in[0][1]*wa.x + in[0][2]*wa.y + in[0][3]*wa.z
                     + in[1][1]*wa.w + in[1][2]*wb.x + in[1][3]*wb.y
                     + in[2][1]*wb.z + in[2][2]*wb.w + in[2][3]*wc;
        }
        __syncthreads();
    }
    int ox = x0 + 2*tx, oy = y0 + ty;
    float* D = dst + (size_t)b*COUT*HW + oy*Ww + ox;
    #pragma unroll
    for (int k = 0; k < KO; k++) {
        float r0 = acc0[k], r1 = acc1[k];
        if (RELU) { r0 = (r0 > 0.f) ? r0 : 0.1f*r0; r1 = (r1 > 0.f) ? r1 : 0.1f*r1; }
        D[(size_t)(ko0 + k)*HW]     = r0;
        D[(size_t)(ko0 + k)*HW + 1] = r1;
    }
}

// ---------------- launch ----------------
extern "C" void kernel_launch(void* const* d_in, const int* in_sizes, int n_in,
                              void* d_out, int out_size) {
    const float* feat0     = (const float*)d_in[0];
    const float* feat1     = (const float*)d_in[1];
    const float* last_feat = (const float*)d_in[2];
    const float* last_flow = (const float*)d_in[3];
    const float* w1 = (const float*)d_in[4];  const float* b1 = (const float*)d_in[5];
    const float* w2 = (const float*)d_in[6];  const float* b2 = (const float*)d_in[7];
    const float* w3 = (const float*)d_in[8];  const float* b3 = (const float*)d_in[9];
    const float* w4 = (const float*)d_in[10]; const float* b4 = (const float*)d_in[11];
    const float* w5 = (const float*)d_in[12]; const float* b5 = (const float*)d_in[13];
    const float* w6 = (const float*)d_in[14]; const float* b6 = (const float*)d_in[15];

    float* out      = (float*)d_out;
    float* flow_out = out;                          // (B,4,H,W) first
    float* feat_out = out + (size_t)Bn*4*HW;        // (B,64,H,W) second

    void* p;
    cudaGetSymbolAddress(&p, g_p1); float* pb1 = (float*)p;
    cudaGetSymbolAddress(&p, g_p2); float* pb2 = (float*)p;

    zero_acc_kernel<<<15600, 1024>>>();
    splat_kernel<<<dim3(960, 2), 256>>>(feat0, feat1, last_flow);
    assemble_kernel<<<960, 256>>>(last_feat, last_flow);
    corr_kernel<<<dim3(20, 12, Bn*9), dim3(16, 16)>>>();
    conv1x1_kernel<<<dim3(240, Bn, 5), 256>>>(w1, b1);
    conv3x3_kernel<160, 128, 8, true ><<<dim3(10, 12, Bn*16), dim3(16, 16)>>>(pb1,      w2, b2, pb2);
    conv3x3_kernel<128, 112, 8, true ><<<dim3(10, 12, Bn*14), dim3(16, 16)>>>(pb2,      w3, b3, pb1);
    conv3x3_kernel<112,  96, 8, true ><<<dim3(10, 12, Bn*12), dim3(16, 16)>>>(pb1,      w4, b4, pb2);
    conv3x3_kernel< 96,  64, 8, true ><<<dim3(10, 12, Bn* 8), dim3(16, 16)>>>(pb2,      w5, b5, feat_out);
    conv3x3_kernel< 64,   4, 4, false><<<dim3(10, 12, Bn* 1), dim3(16, 16)>>>(feat_out, w6, b6, flow_out);
}

// round 14
// speedup vs baseline: 1.0179x; 1.0179x over previous
#include <cuda_runtime.h>
#include <math.h>

#define Bn 4
#define Hh 192
#define Ww 320
#define HW (Hh*Ww)

// ---------------- scratch (static __device__ arrays; no allocation) ----------------
__device__ float g_acc0[(size_t)Bn*65*HW];   // splat accum feat0 (+ones)
__device__ float g_acc1[(size_t)Bn*65*HW];   // splat accum feat1 (+ones)
__device__ float g_X   [(size_t)Bn*277*HW];  // concat input to conv1
__device__ float g_p1  [(size_t)Bn*160*HW];  // ping
__device__ float g_p2  [(size_t)Bn*128*HW];  // pong

// ---------------- zero accumulators ----------------
__global__ void zero_acc_kernel() {
    size_t i = (size_t)blockIdx.x * blockDim.x + threadIdx.x;
    if (i < (size_t)Bn*65*HW) { g_acc0[i] = 0.f; g_acc1[i] = 0.f; }
}

// ---------------- softsplat scatter (atomics) — R2 known-pass ----------------
__global__ void splat_kernel(const float* __restrict__ feat0,
                             const float* __restrict__ feat1,
                             const float* __restrict__ flow) {
    int idx = blockIdx.x * 256 + threadIdx.x;
    if (idx >= Bn*HW) return;
    int f = blockIdx.y;                 // 0: feat0/flow[:2], 1: feat1/flow[2:]
    int b = idx / HW, p = idx % HW;
    int y = p / Ww, x = p % Ww;
    const float* feat = f ? feat1 : feat0;
    float* acc = (f ? g_acc1 : g_acc0) + (size_t)b*65*HW;
    float u = flow[((size_t)b*4 + (f ? 2 : 0))*HW + p] * 0.125f;
    float v = flow[((size_t)b*4 + (f ? 3 : 1))*HW + p] * 0.125f;
    float tx = (float)x + u, ty = (float)y + v;
    float x0f = floorf(tx), y0f = floorf(ty);
    int ix0 = (int)x0f, iy0 = (int)y0f;
    float wx1 = tx - x0f,         wy1 = ty - y0f;
    float wx0 = (x0f + 1.f) - tx, wy0 = (y0f + 1.f) - ty;

    int offs[4]; float wts[4]; int n = 0;
    int   xs[2]  = {ix0, ix0 + 1}, ys2[2] = {iy0, iy0 + 1};
    float wxa[2] = {wx0, wx1},     wya[2] = {wy0, wy1};
    #pragma unroll
    for (int cy = 0; cy < 2; cy++)
        #pragma unroll
        for (int cx = 0; cx < 2; cx++) {
            int xx = xs[cx], yy = ys2[cy];
            if (xx >= 0 && xx < Ww && yy >= 0 && yy < Hh) {
                offs[n] = yy*Ww + xx; wts[n] = wxa[cx]*wya[cy]; n++;
            }
        }
    const float* fb = feat + (size_t)b*64*HW + p;
    for (int c = 0; c < 65; c++) {
        float val = (c < 64) ? fb[(size_t)c*HW] : 1.f;
        float* ap = acc + (size_t)c*HW;
        for (int k = 0; k < n; k++) atomicAdd(ap + offs[k], val * wts[k]);
    }
}

// ---------------- normalize + assemble concat buffer X — R2 known-pass ----------------
// X channels: [0,81) corr, [81,145) f0, [145,209) f1, [209,273) last_feat, [273,277) last_flow
__global__ void assemble_kernel(const float* __restrict__ last_feat,
                                const float* __restrict__ last_flow) {
    int idx = blockIdx.x * 256 + threadIdx.x;
    if (idx >= Bn*HW) return;
    int b = idx / HW, p = idx % HW;
    const float* a0 = g_acc0 + (size_t)b*65*HW + p;
    const float* a1 = g_acc1 + (size_t)b*65*HW + p;
    float n0 = a0[(size_t)64*HW]; n0 = (n0 == 0.f) ? 1.f : n0;
    float n1 = a1[(size_t)64*HW]; n1 = (n1 == 0.f) ? 1.f : n1;
    float* Xb = g_X + (size_t)b*277*HW + p;
    for (int c = 0; c < 64; c++) Xb[(size_t)(81  + c)*HW] = a0[(size_t)c*HW] / n0;
    for (int c = 0; c < 64; c++) Xb[(size_t)(145 + c)*HW] = a1[(size_t)c*HW] / n1;
    const float* lf = last_feat + (size_t)b*64*HW + p;
    for (int c = 0; c < 64; c++) Xb[(size_t)(209 + c)*HW] = lf[(size_t)c*HW];
    const float* lw = last_flow + (size_t)b*4*HW + p;
    for (int c = 0; c < 4;  c++) Xb[(size_t)(273 + c)*HW] = lw[(size_t)c*HW];
}

// ---------------- correlation volume — R2 known-pass ----------------
// grid: (W/16, H/16, B*9), block (16,16)
__global__ void corr_kernel() {
    int z = blockIdx.z;
    int b = z / 9, dyi = z % 9, dy = dyi - 4;
    int x0 = blockIdx.x * 16, y0 = blockIdx.y * 16;
    int tx = threadIdx.x, ty = threadIdx.y;
    __shared__ float s0[16][17];
    __shared__ float s1[16][25];
    float acc[9];
    #pragma unroll
    for (int d = 0; d < 9; d++) acc[d] = 0.f;
    const float* F0 = g_X + ((size_t)b*277 + 81)*HW;
    const float* F1 = g_X + ((size_t)b*277 + 145)*HW;
    int y = y0 + ty, x = x0 + tx;
    for (int c = 0; c < 64; c++) {
        s0[ty][tx] = F0[(size_t)c*HW + y*Ww + x];
        int ys = y + dy;
        int xs = x0 - 4 + tx;
        float v = 0.f;
        if (ys >= 0 && ys < Hh && xs >= 0 && xs < Ww) v = F1[(size_t)c*HW + ys*Ww + xs];
        s1[ty][tx] = v;
        if (tx < 8) {
            int xs2 = x0 + 12 + tx;
            float v2 = 0.f;
            if (ys >= 0 && ys < Hh && xs2 >= 0 && xs2 < Ww) v2 = F1[(size_t)c*HW + ys*Ww + xs2];
            s1[ty][16 + tx] = v2;
        }
        __syncthreads();
        float a = s0[ty][tx];
        #pragma unroll
        for (int d = 0; d < 9; d++) acc[d] += a * s1[ty][tx + d];
        __syncthreads();
    }
    float* V = g_X + (size_t)b*277*HW;
    #pragma unroll
    for (int d = 0; d < 9; d++) {
        float r = acc[d] * (1.f/64.f);
        r = (r > 0.f) ? r : 0.1f * r;
        V[(size_t)(dyi*9 + d)*HW + y*Ww + x] = r;
    }
}

// ---------------- conv1 (1x1, 277 -> 160, lrelu) — R2 known-pass ----------------
// grid (HW/256, B, 160/32), block 256, KO=32
__global__ void conv1x1_kernel(const float* __restrict__ wt,
                               const float* __restrict__ bias) {
    int p   = blockIdx.x * 256 + threadIdx.x;
    int b   = blockIdx.y;
    int ko0 = blockIdx.z * 32;
    __shared__ float wsm[16][32];
    float acc[32];
    #pragma unroll
    for (int k = 0; k < 32; k++) acc[k] = bias[ko0 + k];
    const float* Xb = g_X + (size_t)b*277*HW + p;
    for (int c0 = 0; c0 < 277; c0 += 16) {
        for (int i = threadIdx.x; i < 512; i += 256) {
            int ci = i >> 5, ko = i & 31;
            int cin = c0 + ci;
            wsm[ci][ko] = (cin < 277) ? wt[(size_t)(ko0 + ko)*277 + cin] : 0.f;
        }
        __syncthreads();
        int cmax = 277 - c0; if (cmax > 16) cmax = 16;
        for (int ci = 0; ci < cmax; ci++) {
            float v = Xb[(size_t)(c0 + ci)*HW];
            const float4* wrow = reinterpret_cast<const float4*>(wsm[ci]);
            #pragma unroll
            for (int k4 = 0; k4 < 8; k4++) {
                float4 w = wrow[k4];
                acc[4*k4+0] += v * w.x;
                acc[4*k4+1] += v * w.y;
                acc[4*k4+2] += v * w.z;
                acc[4*k4+3] += v * w.w;
            }
        }
        __syncthreads();
    }
    float* out = g_p1 + (size_t)b*160*HW + p;
    #pragma unroll
    for (int k = 0; k < 32; k++) {
        float r = acc[k];
        r = (r > 0.f) ? r : 0.1f * r;
        out[(size_t)(ko0 + k)*HW] = r;
    }
}

// ---------------- 3x3 conv (pad=1), restructured scalar, FIXED output offset ----
// 64-wide tile, 4 px/thread, KO out-channels, 2 input channels per stage.
// grid ((COUT/KO)*(W/64), H/16, B), block (16,16); blockIdx.x % NG = channel
// group so CTAs sharing an input tile are adjacent (L2-friendly).
template<int CIN, int COUT, int KO, bool RELU>
__global__ __launch_bounds__(256) void conv3x3_s4(const float* __restrict__ src,
                                                  const float* __restrict__ wt,
                                                  const float* __restrict__ bias,
                                                  float* __restrict__ dst) {
    constexpr int NG = COUT / KO;
    int bx  = blockIdx.x;
    int kg  = bx % NG, xt = bx / NG;
    int b   = blockIdx.z;
    int ko0 = kg * KO;
    int x0  = xt * 64, y0 = blockIdx.y * 16;
    int tx  = threadIdx.x, ty = threadIdx.y;
    int tid = ty * 16 + tx;
    __shared__ float s[2][18][67];
    __shared__ float wsm[2][KO][9];
    float acc[KO][4];
    #pragma unroll
    for (int k = 0; k < KO; k++) {
        float bv = bias[ko0 + k];
        #pragma unroll
        for (int px = 0; px < 4; px++) acc[k][px] = bv;
    }
    const float* S = src + (size_t)b*CIN*HW;
    for (int c0 = 0; c0 < CIN; c0 += 2) {
        #pragma unroll
        for (int cs = 0; cs < 2; cs++) {
            const float* Sc = S + (size_t)(c0 + cs)*HW;
            for (int i = tid; i < 18*66; i += 256) {
                int r = i / 66, cc = i % 66;
                int gy = y0 - 1 + r, gx = x0 - 1 + cc;
                float v = 0.f;
                if (gy >= 0 && gy < Hh && gx >= 0 && gx < Ww) v = Sc[gy*Ww + gx];
                s[cs][r][cc] = v;
            }
        }
        for (int i = tid; i < 2*KO*9; i += 256) {
            int cs = i / (KO*9), rr = i % (KO*9), k = rr / 9, q = rr % 9;
            wsm[cs][k][q] = wt[((size_t)(ko0 + k)*CIN + (c0 + cs))*9 + q];
        }
        __syncthreads();
        #pragma unroll
        for (int cs = 0; cs < 2; cs++) {
            float in[3][6];
            #pragma unroll
            for (int r = 0; r < 3; r++)
                #pragma unroll
                for (int cc = 0; cc < 6; cc++) in[r][cc] = s[cs][ty + r][4*tx + cc];
            #pragma unroll
            for (int k = 0; k < KO; k++) {
                float w0 = wsm[cs][k][0], w1 = wsm[cs][k][1], w2 = wsm[cs][k][2];
                float w3 = wsm[cs][k][3], w4 = wsm[cs][k][4], w5 = wsm[cs][k][5];
                float w6 = wsm[cs][k][6], w7 = wsm[cs][k][7], w8 = wsm[cs][k][8];
                #pragma unroll
                for (int px = 0; px < 4; px++) {
                    acc[k][px] += in[0][px+0]*w0 + in[0][px+1]*w1 + in[0][px+2]*w2
                                + in[1][px+0]*w3 + in[1][px+1]*w4 + in[1][px+2]*w5
                                + in[2][px+0]*w6 + in[2][px+1]*w7 + in[2][px+2]*w8;
                }
            }
        }
        __syncthreads();
    }
    int oy = y0 + ty, oxb = x0 + 4*tx;
    float* D = dst + (size_t)b*COUT*HW + oy*Ww + oxb;
    #pragma unroll
    for (int k = 0; k < KO; k++) {
        float r0 = acc[k][0], r1 = acc[k][1], r2 = acc[k][2], r3 = acc[k][3];
        if (RELU) {
            r0 = (r0 > 0.f) ? r0 : 0.1f*r0;
            r1 = (r1 > 0.f) ? r1 : 0.1f*r1;
            r2 = (r2 > 0.f) ? r2 : 0.1f*r2;
            r3 = (r3 > 0.f) ? r3 : 0.1f*r3;
        }
        // FIX: output channel offset ko0 (was missing in R3/R4/R7/R11/R12 stores)
        *reinterpret_cast<float4*>(&D[(size_t)(ko0 + k)*HW]) = make_float4(r0, r1, r2, r3);
    }
}

// ---------------- launch ----------------
extern "C" void kernel_launch(void* const* d_in, const int* in_sizes, int n_in,
                              void* d_out, int out_size) {
    const float* feat0     = (const float*)d_in[0];
    const float* feat1     = (const float*)d_in[1];
    const float* last_feat = (const float*)d_in[2];
    const float* last_flow = (const float*)d_in[3];
    const float* w1 = (const float*)d_in[4];  const float* b1 = (const float*)d_in[5];
    const float* w2 = (const float*)d_in[6];  const float* b2 = (const float*)d_in[7];
    const float* w3 = (const float*)d_in[8];  const float* b3 = (const float*)d_in[9];
    const float* w4 = (const float*)d_in[10]; const float* b4 = (const float*)d_in[11];
    const float* w5 = (const float*)d_in[12]; const float* b5 = (const float*)d_in[13];
    const float* w6 = (const float*)d_in[14]; const float* b6 = (const float*)d_in[15];

    float* out      = (float*)d_out;
    float* flow_out = out;                          // (B,4,H,W) first
    float* feat_out = out + (size_t)Bn*4*HW;        // (B,64,H,W) second

    void* p;
    cudaGetSymbolAddress(&p, g_p1); float* pb1 = (float*)p;
    cudaGetSymbolAddress(&p, g_p2); float* pb2 = (float*)p;

    zero_acc_kernel<<<15600, 1024>>>();
    splat_kernel<<<dim3(960, 2), 256>>>(feat0, feat1, last_flow);
    assemble_kernel<<<960, 256>>>(last_feat, last_flow);
    corr_kernel<<<dim3(20, 12, Bn*9), dim3(16, 16)>>>();
    conv1x1_kernel<<<dim3(240, Bn, 5), 256>>>(w1, b1);
    conv3x3_s4<160, 128, 8, true ><<<dim3(16*5, 12, Bn), dim3(16, 16)>>>(pb1,      w2, b2, pb2);
    conv3x3_s4<128, 112, 8, true ><<<dim3(14*5, 12, Bn), dim3(16, 16)>>>(pb2,      w3, b3, pb1);
    conv3x3_s4<112,  96, 8, true ><<<dim3(12*5, 12, Bn), dim3(16, 16)>>>(pb1,      w4, b4, pb2);
    conv3x3_s4< 96,  64, 8, true ><<<dim3( 8*5, 12, Bn), dim3(16, 16)>>>(pb2,      w5, b5, feat_out);
    conv3x3_s4< 64,   4, 4, false><<<dim3( 1*5, 12, Bn), dim3(16, 16)>>>(feat_out, w6, b6, flow_out);
}